// round 1
// baseline (speedup 1.0000x reference)
#include <cuda_runtime.h>
#include <math.h>

// Problem constants
#define Bn 8
#define C  256
#define CK 32
#define N  4096

// ---------------- scratch (global __device__, no allocs) ----------------
__device__ float d_f[Bn * CK * N];            // f[b][k][n]   4 MB
__device__ float d_g[Bn * CK * N];            // g[b][k][n]   4 MB
__device__ float d_hp[(size_t)Bn * N * C];    // h'[b][n][c] 32 MB (pre-scaled by 1/Z)
__device__ float d_hwT[C * C];                // h_w transposed [c][o]
__device__ float d_m[Bn * N];                 // column max  m_j
__device__ float d_rz[Bn * N];                // 1 / Z_j

// ---------------- transpose h_w: [o][c] -> [c][o] ----------------
__global__ void k_transpose_hw(const float* __restrict__ hw) {
    int idx = blockIdx.x * 256 + threadIdx.x;   // 65536 elements
    int c = idx >> 8, o = idx & 255;
    d_hwT[c * C + o] = hw[o * C + c];
}

// ---------------- f,g projections: out[b][o<32][n] ----------------
// grid (32 nb, 8 b, 2 which), 256 threads
__global__ void k_proj_fg(const float* __restrict__ x,
                          const float* __restrict__ fw, const float* __restrict__ fb,
                          const float* __restrict__ gw, const float* __restrict__ gb) {
    __shared__ float xs[32][128];
    __shared__ float ws[32][32];   // ws[cc][o]
    int nb = blockIdx.x, b = blockIdx.y, which = blockIdx.z;
    const float* w    = which ? gw : fw;
    const float* bias = which ? gb : fb;
    float* o = which ? d_g : d_f;
    int tid = threadIdx.x;
    int oq = tid & 3;       // 4 groups of 8 outputs
    int nq = tid >> 2;      // 64 groups of 2 pixels
    float acc[8][2] = {};

    for (int c0 = 0; c0 < 256; c0 += 32) {
        __syncthreads();
        for (int t = tid; t < 1024; t += 256)
            ((float4*)xs)[t] = ((const float4*)x)[ ((size_t)b * C + c0 + (t >> 5)) * 1024
                                                   + (size_t)nb * 32 + (t & 31) ];
        for (int t = tid; t < 1024; t += 256) {
            int oo = t >> 5, cc = t & 31;
            ws[cc][oo] = w[oo * C + c0 + cc];
        }
        __syncthreads();
#pragma unroll
        for (int k = 0; k < 32; k++) {
            float x0 = xs[k][nq * 2], x1 = xs[k][nq * 2 + 1];
#pragma unroll
            for (int u = 0; u < 8; u++) {
                float wv = ws[k][oq * 8 + u];
                acc[u][0] += wv * x0;
                acc[u][1] += wv * x1;
            }
        }
    }
#pragma unroll
    for (int u = 0; u < 8; u++) {
        int oo = oq * 8 + u;
        float bz = bias[oo];
        size_t base = ((size_t)(b * CK + oo)) * N + nb * 128 + nq * 2;
        o[base]     = acc[u][0] + bz;
        o[base + 1] = acc[u][1] + bz;
    }
}

// ---------------- pass 1: column softmax stats over i ----------------
// grid (32 jb, 8 b), 256 threads. dyn smem = (4096+4096+128*132)*4 = 100352 B
__global__ void k_stats() {
    extern __shared__ float sm[];
    float* sGt = sm;                 // [32][128]  g[k][j]
    float* sFt = sGt + 32 * 128;     // [32][128]  f[k][i]
    float* sS  = sFt + 32 * 128;     // [128][132] S tile (padded)
    int jb = blockIdx.x, b = blockIdx.y;
    int tid = threadIdx.x, ti = tid & 15, tj = tid >> 4;

    // g tile fixed for the whole block
    for (int t = tid; t < 1024; t += 256)
        ((float4*)sGt)[t] = ((const float4*)d_g)[ (size_t)(b * CK + (t >> 5)) * 1024
                                                  + jb * 32 + (t & 31) ];

    float m = -INFINITY, z = 0.f;
    int rj = tid & 127, half = tid >> 7;

    for (int ib = 0; ib < 32; ib++) {
        __syncthreads();
        for (int t = tid; t < 1024; t += 256)
            ((float4*)sFt)[t] = ((const float4*)d_f)[ (size_t)(b * CK + (t >> 5)) * 1024
                                                      + ib * 32 + (t & 31) ];
        __syncthreads();

        float e[8][8];
#pragma unroll
        for (int r = 0; r < 8; r++)
#pragma unroll
            for (int s = 0; s < 8; s++) e[r][s] = 0.f;

#pragma unroll 8
        for (int k = 0; k < 32; k++) {
            float a[8], g[8];
            *(float4*)(a)     = *(float4*)&sFt[k * 128 + ti * 8];
            *(float4*)(a + 4) = *(float4*)&sFt[k * 128 + ti * 8 + 4];
            *(float4*)(g)     = *(float4*)&sGt[k * 128 + tj * 8];
            *(float4*)(g + 4) = *(float4*)&sGt[k * 128 + tj * 8 + 4];
#pragma unroll
            for (int r = 0; r < 8; r++)
#pragma unroll
                for (int s = 0; s < 8; s++) e[r][s] += a[r] * g[s];
        }
#pragma unroll
        for (int r = 0; r < 8; r++) {
            *(float4*)&sS[(ti * 8 + r) * 132 + tj * 8]     = make_float4(e[r][0], e[r][1], e[r][2], e[r][3]);
            *(float4*)&sS[(ti * 8 + r) * 132 + tj * 8 + 4] = make_float4(e[r][4], e[r][5], e[r][6], e[r][7]);
        }
        __syncthreads();

        // online column softmax stats: this thread owns column rj, rows [half*64, half*64+64)
        for (int i = half * 64; i < half * 64 + 64; i++) {
            float v = sS[i * 132 + rj];
            if (v <= m) {
                z += __expf(v - m);
            } else {
                z = z * __expf(m - v) + 1.f;
                m = v;
            }
        }
    }
    __syncthreads();
    if (tid >= 128) { sS[rj] = m; sS[128 + rj] = z; }
    __syncthreads();
    if (tid < 128) {
        float m1 = sS[rj], z1 = sS[128 + rj];
        float nm = fmaxf(m, m1);
        float zz = z * __expf(m - nm) + z1 * __expf(m1 - nm);
        d_m[b * N + jb * 128 + rj]  = nm;
        d_rz[b * N + jb * 128 + rj] = 1.f / zz;
    }
}

// ---------------- h projection, fused with 1/Z scaling: h'[b][n][c] ----------------
// grid (32 nb, 8 b, 2 ch), 256 threads
__global__ void k_proj_h(const float* __restrict__ x, const float* __restrict__ hb) {
    __shared__ float xs[32][128];
    __shared__ float ws[32][128];
    int nb = blockIdx.x, b = blockIdx.y, ch = blockIdx.z;
    int tid = threadIdx.x, tn = tid & 15, tc = tid >> 4;
    float acc[8][8] = {};

    for (int c0 = 0; c0 < 256; c0 += 32) {
        __syncthreads();
        for (int t = tid; t < 1024; t += 256) {
            ((float4*)xs)[t] = ((const float4*)x)[ ((size_t)b * C + c0 + (t >> 5)) * 1024
                                                   + (size_t)nb * 32 + (t & 31) ];
            ((float4*)ws)[t] = ((const float4*)d_hwT)[ (size_t)(c0 + (t >> 5)) * 64
                                                       + ch * 32 + (t & 31) ];
        }
        __syncthreads();
#pragma unroll 8
        for (int k = 0; k < 32; k++) {
            float a[8], w[8];
            *(float4*)(a)     = *(float4*)&xs[k][tn * 8];
            *(float4*)(a + 4) = *(float4*)&xs[k][tn * 8 + 4];
            *(float4*)(w)     = *(float4*)&ws[k][tc * 8];
            *(float4*)(w + 4) = *(float4*)&ws[k][tc * 8 + 4];
#pragma unroll
            for (int r = 0; r < 8; r++)
#pragma unroll
                for (int s = 0; s < 8; s++) acc[r][s] += a[r] * w[s];
        }
    }
#pragma unroll
    for (int r = 0; r < 8; r++) {
        int n = nb * 128 + tn * 8 + r;
        float rz = d_rz[b * N + n];
        size_t base = ((size_t)b * N + n) * C + ch * 128 + tc * 8;
        float4 o0, o1;
        o0.x = (acc[r][0] + hb[ch * 128 + tc * 8 + 0]) * rz;
        o0.y = (acc[r][1] + hb[ch * 128 + tc * 8 + 1]) * rz;
        o0.z = (acc[r][2] + hb[ch * 128 + tc * 8 + 2]) * rz;
        o0.w = (acc[r][3] + hb[ch * 128 + tc * 8 + 3]) * rz;
        o1.x = (acc[r][4] + hb[ch * 128 + tc * 8 + 4]) * rz;
        o1.y = (acc[r][5] + hb[ch * 128 + tc * 8 + 5]) * rz;
        o1.z = (acc[r][6] + hb[ch * 128 + tc * 8 + 6]) * rz;
        o1.w = (acc[r][7] + hb[ch * 128 + tc * 8 + 7]) * rz;
        *(float4*)&d_hp[base]     = o0;
        *(float4*)&d_hp[base + 4] = o1;
    }
}

// ---------------- pass 2: O^T[i][c] = sum_j exp(S[i][j]-m_j) * h'[j][c]; out = O + x ----------------
// grid (32 ib, 8 b, 2 ch), 256 threads. dyn smem = (4096+4096+128+16384+16384)*4 = 164352 B
__global__ void k_out(const float* __restrict__ x, float* __restrict__ out) {
    extern __shared__ float sm[];
    float* sFt = sm;                 // [32][128] f[k][i]
    float* sGt = sFt + 4096;         // [32][128] g[k][j]
    float* sM  = sGt + 4096;         // [128]
    float* sEt = sM + 128;           // [128][128] E^T[j][i]
    float* sH  = sEt + 16384;        // [128][128] h'[j][c]
    int ib = blockIdx.x, b = blockIdx.y, ch = blockIdx.z;
    int tid = threadIdx.x, ti = tid & 15, tj = tid >> 4;

    // f tile fixed for the whole block (i-range fixed)
    for (int t = tid; t < 1024; t += 256)
        ((float4*)sFt)[t] = ((const float4*)d_f)[ (size_t)(b * CK + (t >> 5)) * 1024
                                                  + ib * 32 + (t & 31) ];
    float acc[8][8] = {};

    for (int jb = 0; jb < 32; jb++) {
        __syncthreads();
        for (int t = tid; t < 1024; t += 256)
            ((float4*)sGt)[t] = ((const float4*)d_g)[ (size_t)(b * CK + (t >> 5)) * 1024
                                                      + jb * 32 + (t & 31) ];
        if (tid < 128) sM[tid] = d_m[b * N + jb * 128 + tid];
        for (int t = tid; t < 4096; t += 256)
            ((float4*)sH)[t] = ((const float4*)d_hp)[ ((size_t)b * N + jb * 128 + (t >> 5)) * 64
                                                      + ch * 32 + (t & 31) ];
        __syncthreads();

        // S tile (K=32)
        float e[8][8];
#pragma unroll
        for (int r = 0; r < 8; r++)
#pragma unroll
            for (int s = 0; s < 8; s++) e[r][s] = 0.f;
#pragma unroll 8
        for (int k = 0; k < 32; k++) {
            float a[8], g[8];
            *(float4*)(a)     = *(float4*)&sFt[k * 128 + ti * 8];
            *(float4*)(a + 4) = *(float4*)&sFt[k * 128 + ti * 8 + 4];
            *(float4*)(g)     = *(float4*)&sGt[k * 128 + tj * 8];
            *(float4*)(g + 4) = *(float4*)&sGt[k * 128 + tj * 8 + 4];
#pragma unroll
            for (int r = 0; r < 8; r++)
#pragma unroll
                for (int s = 0; s < 8; s++) e[r][s] += a[r] * g[s];
        }
        // E^T[j][i] = exp(S - m_j)
#pragma unroll
        for (int s = 0; s < 8; s++) {
            float mj = sM[tj * 8 + s];
            float4 v0 = make_float4(__expf(e[0][s] - mj), __expf(e[1][s] - mj),
                                    __expf(e[2][s] - mj), __expf(e[3][s] - mj));
            float4 v1 = make_float4(__expf(e[4][s] - mj), __expf(e[5][s] - mj),
                                    __expf(e[6][s] - mj), __expf(e[7][s] - mj));
            *(float4*)&sEt[(tj * 8 + s) * 128 + ti * 8]     = v0;
            *(float4*)&sEt[(tj * 8 + s) * 128 + ti * 8 + 4] = v1;
        }
        __syncthreads();

        // O^T tile += E^T(k=j) x h'(k=j): K=128
#pragma unroll 4
        for (int k = 0; k < 128; k++) {
            float a[8], h[8];
            *(float4*)(a)     = *(float4*)&sEt[k * 128 + ti * 8];
            *(float4*)(a + 4) = *(float4*)&sEt[k * 128 + ti * 8 + 4];
            *(float4*)(h)     = *(float4*)&sH[k * 128 + tj * 8];
            *(float4*)(h + 4) = *(float4*)&sH[k * 128 + tj * 8 + 4];
#pragma unroll
            for (int r = 0; r < 8; r++)
#pragma unroll
                for (int s = 0; s < 8; s++) acc[r][s] += a[r] * h[s];
        }
    }

    // epilogue: out[b][c][i] = O + x  (gamma = 1)
#pragma unroll
    for (int s = 0; s < 8; s++) {
        int c = ch * 128 + tj * 8 + s;
        size_t base = ((size_t)b * C + c) * N + ib * 128 + ti * 8;
        float4 x0 = *(const float4*)&x[base];
        float4 x1 = *(const float4*)&x[base + 4];
        float4 o0 = make_float4(acc[0][s] + x0.x, acc[1][s] + x0.y,
                                acc[2][s] + x0.z, acc[3][s] + x0.w);
        float4 o1 = make_float4(acc[4][s] + x1.x, acc[5][s] + x1.y,
                                acc[6][s] + x1.z, acc[7][s] + x1.w);
        *(float4*)&out[base]     = o0;
        *(float4*)&out[base + 4] = o1;
    }
}

// ---------------- launch ----------------
extern "C" void kernel_launch(void* const* d_in, const int* in_sizes, int n_in,
                              void* d_out, int out_size) {
    const float* x  = (const float*)d_in[0];
    const float* fw = (const float*)d_in[1];
    const float* fb = (const float*)d_in[2];
    const float* gw = (const float*)d_in[3];
    const float* gb = (const float*)d_in[4];
    const float* hw = (const float*)d_in[5];
    const float* hb = (const float*)d_in[6];
    float* out = (float*)d_out;

    const int SMEM_B = (4096 + 4096 + 128 * 132) * 4;                    // 100352
    const int SMEM_C = (4096 + 4096 + 128 + 16384 + 16384) * 4;         // 164352
    cudaFuncSetAttribute(k_stats, cudaFuncAttributeMaxDynamicSharedMemorySize, SMEM_B);
    cudaFuncSetAttribute(k_out,   cudaFuncAttributeMaxDynamicSharedMemorySize, SMEM_C);

    k_transpose_hw<<<256, 256>>>(hw);
    k_proj_fg<<<dim3(32, 8, 2), 256>>>(x, fw, fb, gw, gb);
    k_stats<<<dim3(32, 8), 256, SMEM_B>>>();
    k_proj_h<<<dim3(32, 8, 2), 256>>>(x, hb);
    k_out<<<dim3(32, 8, 2), 256, SMEM_C>>>(x, out);
}

// round 2
// speedup vs baseline: 1.0004x; 1.0004x over previous
#include <cuda_runtime.h>
#include <math.h>

// Problem constants
#define Bn 8
#define C  256
#define CK 32
#define N  4096

// ---------------- scratch (global __device__, no allocs) ----------------
__device__ float d_f[Bn * CK * N];            // f[b][k][n]   4 MB
__device__ float d_g[Bn * CK * N];            // g[b][k][n]   4 MB
__device__ float d_hp[(size_t)Bn * N * C];    // h'[b][n][c] 32 MB (pre-scaled by 1/Z)
__device__ float d_hwT[C * C];                // h_w transposed [c][o]
__device__ float d_m[Bn * N];                 // column max  m_j
__device__ float d_rz[Bn * N];                // 1 / Z_j

// ---------------- transpose h_w: [o][c] -> [c][o] ----------------
__global__ void k_transpose_hw(const float* __restrict__ hw) {
    int idx = blockIdx.x * 256 + threadIdx.x;   // 65536 elements
    int c = idx >> 8, o = idx & 255;
    d_hwT[c * C + o] = hw[o * C + c];
}

// ---------------- f,g projections: out[b][o<32][n] ----------------
// grid (32 nb, 8 b, 2 which), 256 threads
__global__ void k_proj_fg(const float* __restrict__ x,
                          const float* __restrict__ fw, const float* __restrict__ fb,
                          const float* __restrict__ gw, const float* __restrict__ gb) {
    __shared__ float xs[32][128];
    __shared__ float ws[32][32];   // ws[cc][o]
    int nb = blockIdx.x, b = blockIdx.y, which = blockIdx.z;
    const float* w    = which ? gw : fw;
    const float* bias = which ? gb : fb;
    float* o = which ? d_g : d_f;
    int tid = threadIdx.x;
    int oq = tid & 3;       // 4 groups of 8 outputs
    int nq = tid >> 2;      // 64 groups of 2 pixels
    float acc[8][2] = {};

    for (int c0 = 0; c0 < 256; c0 += 32) {
        __syncthreads();
        for (int t = tid; t < 1024; t += 256)
            ((float4*)xs)[t] = ((const float4*)x)[ ((size_t)b * C + c0 + (t >> 5)) * 1024
                                                   + (size_t)nb * 32 + (t & 31) ];
        for (int t = tid; t < 1024; t += 256) {
            int oo = t >> 5, cc = t & 31;
            ws[cc][oo] = w[oo * C + c0 + cc];
        }
        __syncthreads();
#pragma unroll
        for (int k = 0; k < 32; k++) {
            float x0 = xs[k][nq * 2], x1 = xs[k][nq * 2 + 1];
#pragma unroll
            for (int u = 0; u < 8; u++) {
                float wv = ws[k][oq * 8 + u];
                acc[u][0] += wv * x0;
                acc[u][1] += wv * x1;
            }
        }
    }
#pragma unroll
    for (int u = 0; u < 8; u++) {
        int oo = oq * 8 + u;
        float bz = bias[oo];
        size_t base = ((size_t)(b * CK + oo)) * N + nb * 128 + nq * 2;
        o[base]     = acc[u][0] + bz;
        o[base + 1] = acc[u][1] + bz;
    }
}

// ---------------- pass 1: column softmax stats over i ----------------
// grid (32 jb, 8 b), 256 threads. dyn smem = (4096+4096+128*132)*4 = 100352 B
__global__ void k_stats() {
    extern __shared__ float sm[];
    float* sGt = sm;                 // [32][128]  g[k][j]
    float* sFt = sGt + 32 * 128;     // [32][128]  f[k][i]
    float* sS  = sFt + 32 * 128;     // [128][132] S tile (padded)
    int jb = blockIdx.x, b = blockIdx.y;
    int tid = threadIdx.x, ti = tid & 15, tj = tid >> 4;

    // g tile fixed for the whole block
    for (int t = tid; t < 1024; t += 256)
        ((float4*)sGt)[t] = ((const float4*)d_g)[ (size_t)(b * CK + (t >> 5)) * 1024
                                                  + jb * 32 + (t & 31) ];

    float m = -INFINITY, z = 0.f;
    int rj = tid & 127, half = tid >> 7;

    for (int ib = 0; ib < 32; ib++) {
        __syncthreads();
        for (int t = tid; t < 1024; t += 256)
            ((float4*)sFt)[t] = ((const float4*)d_f)[ (size_t)(b * CK + (t >> 5)) * 1024
                                                      + ib * 32 + (t & 31) ];
        __syncthreads();

        float e[8][8];
#pragma unroll
        for (int r = 0; r < 8; r++)
#pragma unroll
            for (int s = 0; s < 8; s++) e[r][s] = 0.f;

#pragma unroll 8
        for (int k = 0; k < 32; k++) {
            float a[8], g[8];
            *(float4*)(a)     = *(float4*)&sFt[k * 128 + ti * 8];
            *(float4*)(a + 4) = *(float4*)&sFt[k * 128 + ti * 8 + 4];
            *(float4*)(g)     = *(float4*)&sGt[k * 128 + tj * 8];
            *(float4*)(g + 4) = *(float4*)&sGt[k * 128 + tj * 8 + 4];
#pragma unroll
            for (int r = 0; r < 8; r++)
#pragma unroll
                for (int s = 0; s < 8; s++) e[r][s] += a[r] * g[s];
        }
#pragma unroll
        for (int r = 0; r < 8; r++) {
            *(float4*)&sS[(ti * 8 + r) * 132 + tj * 8]     = make_float4(e[r][0], e[r][1], e[r][2], e[r][3]);
            *(float4*)&sS[(ti * 8 + r) * 132 + tj * 8 + 4] = make_float4(e[r][4], e[r][5], e[r][6], e[r][7]);
        }
        __syncthreads();

        // online column softmax stats: this thread owns column rj, rows [half*64, half*64+64)
        for (int i = half * 64; i < half * 64 + 64; i++) {
            float v = sS[i * 132 + rj];
            if (v <= m) {
                z += __expf(v - m);
            } else {
                z = z * __expf(m - v) + 1.f;
                m = v;
            }
        }
    }
    __syncthreads();
    if (tid >= 128) { sS[rj] = m; sS[128 + rj] = z; }
    __syncthreads();
    if (tid < 128) {
        float m1 = sS[rj], z1 = sS[128 + rj];
        float nm = fmaxf(m, m1);
        float zz = z * __expf(m - nm) + z1 * __expf(m1 - nm);
        d_m[b * N + jb * 128 + rj]  = nm;
        d_rz[b * N + jb * 128 + rj] = 1.f / zz;
    }
}

// ---------------- h projection, fused with 1/Z scaling: h'[b][n][c] ----------------
// grid (32 nb, 8 b, 2 ch), 256 threads
__global__ void k_proj_h(const float* __restrict__ x, const float* __restrict__ hb) {
    __shared__ float xs[32][128];
    __shared__ float ws[32][128];
    int nb = blockIdx.x, b = blockIdx.y, ch = blockIdx.z;
    int tid = threadIdx.x, tn = tid & 15, tc = tid >> 4;
    float acc[8][8] = {};

    for (int c0 = 0; c0 < 256; c0 += 32) {
        __syncthreads();
        for (int t = tid; t < 1024; t += 256) {
            ((float4*)xs)[t] = ((const float4*)x)[ ((size_t)b * C + c0 + (t >> 5)) * 1024
                                                   + (size_t)nb * 32 + (t & 31) ];
            ((float4*)ws)[t] = ((const float4*)d_hwT)[ (size_t)(c0 + (t >> 5)) * 64
                                                       + ch * 32 + (t & 31) ];
        }
        __syncthreads();
#pragma unroll 8
        for (int k = 0; k < 32; k++) {
            float a[8], w[8];
            *(float4*)(a)     = *(float4*)&xs[k][tn * 8];
            *(float4*)(a + 4) = *(float4*)&xs[k][tn * 8 + 4];
            *(float4*)(w)     = *(float4*)&ws[k][tc * 8];
            *(float4*)(w + 4) = *(float4*)&ws[k][tc * 8 + 4];
#pragma unroll
            for (int r = 0; r < 8; r++)
#pragma unroll
                for (int s = 0; s < 8; s++) acc[r][s] += a[r] * w[s];
        }
    }
#pragma unroll
    for (int r = 0; r < 8; r++) {
        int n = nb * 128 + tn * 8 + r;
        float rz = d_rz[b * N + n];
        size_t base = ((size_t)b * N + n) * C + ch * 128 + tc * 8;
        float4 o0, o1;
        o0.x = (acc[r][0] + hb[ch * 128 + tc * 8 + 0]) * rz;
        o0.y = (acc[r][1] + hb[ch * 128 + tc * 8 + 1]) * rz;
        o0.z = (acc[r][2] + hb[ch * 128 + tc * 8 + 2]) * rz;
        o0.w = (acc[r][3] + hb[ch * 128 + tc * 8 + 3]) * rz;
        o1.x = (acc[r][4] + hb[ch * 128 + tc * 8 + 4]) * rz;
        o1.y = (acc[r][5] + hb[ch * 128 + tc * 8 + 5]) * rz;
        o1.z = (acc[r][6] + hb[ch * 128 + tc * 8 + 6]) * rz;
        o1.w = (acc[r][7] + hb[ch * 128 + tc * 8 + 7]) * rz;
        *(float4*)&d_hp[base]     = o0;
        *(float4*)&d_hp[base + 4] = o1;
    }
}

// ---------------- pass 2: O^T[i][c] = sum_j exp(S[i][j]-m_j) * h'[j][c]; out = O + x ----------------
// grid (32 ib, 8 b, 2 ch), 256 threads. dyn smem = (4096+4096+128+16384+16384)*4 = 164352 B
__global__ void k_out(const float* __restrict__ x, float* __restrict__ out) {
    extern __shared__ float sm[];
    float* sFt = sm;                 // [32][128] f[k][i]
    float* sGt = sFt + 4096;         // [32][128] g[k][j]
    float* sM  = sGt + 4096;         // [128]
    float* sEt = sM + 128;           // [128][128] E^T[j][i]
    float* sH  = sEt + 16384;        // [128][128] h'[j][c]
    int ib = blockIdx.x, b = blockIdx.y, ch = blockIdx.z;
    int tid = threadIdx.x, ti = tid & 15, tj = tid >> 4;

    // f tile fixed for the whole block (i-range fixed)
    for (int t = tid; t < 1024; t += 256)
        ((float4*)sFt)[t] = ((const float4*)d_f)[ (size_t)(b * CK + (t >> 5)) * 1024
                                                  + ib * 32 + (t & 31) ];
    float acc[8][8] = {};

    for (int jb = 0; jb < 32; jb++) {
        __syncthreads();
        for (int t = tid; t < 1024; t += 256)
            ((float4*)sGt)[t] = ((const float4*)d_g)[ (size_t)(b * CK + (t >> 5)) * 1024
                                                      + jb * 32 + (t & 31) ];
        if (tid < 128) sM[tid] = d_m[b * N + jb * 128 + tid];
        for (int t = tid; t < 4096; t += 256)
            ((float4*)sH)[t] = ((const float4*)d_hp)[ ((size_t)b * N + jb * 128 + (t >> 5)) * 64
                                                      + ch * 32 + (t & 31) ];
        __syncthreads();

        // S tile (K=32)
        float e[8][8];
#pragma unroll
        for (int r = 0; r < 8; r++)
#pragma unroll
            for (int s = 0; s < 8; s++) e[r][s] = 0.f;
#pragma unroll 8
        for (int k = 0; k < 32; k++) {
            float a[8], g[8];
            *(float4*)(a)     = *(float4*)&sFt[k * 128 + ti * 8];
            *(float4*)(a + 4) = *(float4*)&sFt[k * 128 + ti * 8 + 4];
            *(float4*)(g)     = *(float4*)&sGt[k * 128 + tj * 8];
            *(float4*)(g + 4) = *(float4*)&sGt[k * 128 + tj * 8 + 4];
#pragma unroll
            for (int r = 0; r < 8; r++)
#pragma unroll
                for (int s = 0; s < 8; s++) e[r][s] += a[r] * g[s];
        }
        // E^T[j][i] = exp(S - m_j)
#pragma unroll
        for (int s = 0; s < 8; s++) {
            float mj = sM[tj * 8 + s];
            float4 v0 = make_float4(__expf(e[0][s] - mj), __expf(e[1][s] - mj),
                                    __expf(e[2][s] - mj), __expf(e[3][s] - mj));
            float4 v1 = make_float4(__expf(e[4][s] - mj), __expf(e[5][s] - mj),
                                    __expf(e[6][s] - mj), __expf(e[7][s] - mj));
            *(float4*)&sEt[(tj * 8 + s) * 128 + ti * 8]     = v0;
            *(float4*)&sEt[(tj * 8 + s) * 128 + ti * 8 + 4] = v1;
        }
        __syncthreads();

        // O^T tile += E^T(k=j) x h'(k=j): K=128
#pragma unroll 4
        for (int k = 0; k < 128; k++) {
            float a[8], h[8];
            *(float4*)(a)     = *(float4*)&sEt[k * 128 + ti * 8];
            *(float4*)(a + 4) = *(float4*)&sEt[k * 128 + ti * 8 + 4];
            *(float4*)(h)     = *(float4*)&sH[k * 128 + tj * 8];
            *(float4*)(h + 4) = *(float4*)&sH[k * 128 + tj * 8 + 4];
#pragma unroll
            for (int r = 0; r < 8; r++)
#pragma unroll
                for (int s = 0; s < 8; s++) acc[r][s] += a[r] * h[s];
        }
    }

    // epilogue: out[b][c][i] = O + x  (gamma = 1)
#pragma unroll
    for (int s = 0; s < 8; s++) {
        int c = ch * 128 + tj * 8 + s;
        size_t base = ((size_t)b * C + c) * N + ib * 128 + ti * 8;
        float4 x0 = *(const float4*)&x[base];
        float4 x1 = *(const float4*)&x[base + 4];
        float4 o0 = make_float4(acc[0][s] + x0.x, acc[1][s] + x0.y,
                                acc[2][s] + x0.z, acc[3][s] + x0.w);
        float4 o1 = make_float4(acc[4][s] + x1.x, acc[5][s] + x1.y,
                                acc[6][s] + x1.z, acc[7][s] + x1.w);
        *(float4*)&out[base]     = o0;
        *(float4*)&out[base + 4] = o1;
    }
}

// ---------------- launch ----------------
extern "C" void kernel_launch(void* const* d_in, const int* in_sizes, int n_in,
                              void* d_out, int out_size) {
    const float* x  = (const float*)d_in[0];
    const float* fw = (const float*)d_in[1];
    const float* fb = (const float*)d_in[2];
    const float* gw = (const float*)d_in[3];
    const float* gb = (const float*)d_in[4];
    const float* hw = (const float*)d_in[5];
    const float* hb = (const float*)d_in[6];
    float* out = (float*)d_out;

    const int SMEM_B = (4096 + 4096 + 128 * 132) * 4;                    // 100352
    const int SMEM_C = (4096 + 4096 + 128 + 16384 + 16384) * 4;         // 164352
    cudaFuncSetAttribute(k_stats, cudaFuncAttributeMaxDynamicSharedMemorySize, SMEM_B);
    cudaFuncSetAttribute(k_out,   cudaFuncAttributeMaxDynamicSharedMemorySize, SMEM_C);

    k_transpose_hw<<<256, 256>>>(hw);
    k_proj_fg<<<dim3(32, 8, 2), 256>>>(x, fw, fb, gw, gb);
    k_stats<<<dim3(32, 8), 256, SMEM_B>>>();
    k_proj_h<<<dim3(32, 8, 2), 256>>>(x, hb);
    k_out<<<dim3(32, 8, 2), 256, SMEM_C>>>(x, out);
}